// round 9
// baseline (speedup 1.0000x reference)
#include <cuda_runtime.h>
#include <cfloat>

#define NN 128

// Ti(k) = 16 << min(3, ctz(base+k)) with base ≡ 0 (mod 16)  => depends only on k=i&15.
__device__ __forceinline__ constexpr int ti_of(int k) {
    return (k == 0 || k == 8) ? 128 : (k & 1) ? 16 : (k & 2) ? 32 : 64;
}

__global__ void __launch_bounds__(256)
sparse_maxpool_kernel(const float* __restrict__ x, float* __restrict__ out) {
    const int bd   = blockIdx.x;            // one (b,d) pair per block
    const int warp = threadIdx.x >> 5;      // 8 warps, warp w owns rows [16w, 16w+15]
    const int lane = threadIdx.x & 31;
    const int jb   = lane << 2;             // this lane's 4 columns: jb..jb+3
    const int base = warp << 4;
    const int srcq = base >> 2;             // lane index holding x[base..base+3]

    // Every lane loads its 4 columns of x (512B row; L1-broadcast across warps).
    const float4 xv = __ldg(((const float4*)(x + (size_t)bd * NN)) + lane);

    // Per-element column thresholds: Tj = 16 << min(3, ctz(j+1)), loop-invariant.
    const unsigned Tj0 = 16u << min(3, __ffs(jb + 1) - 1);
    const unsigned Tj1 = 16u << min(3, __ffs(jb + 2) - 1);
    const unsigned Tj2 = 16u << min(3, __ffs(jb + 3) - 1);
    const unsigned Tj3 = 16u << min(3, __ffs(jb + 4) - 1);

    // Init m_e = max(x[base+16 .. j_e]) for j_e >= base+16, else -inf.
    float m0, m1, m2, m3;
    {
        const bool keep = (lane >= srcq + 4);
        float p0 = keep ? xv.x : -FLT_MAX;
        float p1 = fmaxf(p0, keep ? xv.y : -FLT_MAX);
        float p2 = fmaxf(p1, keep ? xv.z : -FLT_MAX);
        float p3 = fmaxf(p2, keep ? xv.w : -FLT_MAX);
        float s = p3;
        #pragma unroll
        for (int d = 1; d < 32; d <<= 1) {
            float u = __shfl_up_sync(0xffffffffu, s, d);
            if (lane >= d) s = fmaxf(s, u);
        }
        float excl = __shfl_up_sync(0xffffffffu, s, 1);
        if (lane == 0) excl = -FLT_MAX;
        m0 = fmaxf(excl, p0);
        m1 = fmaxf(excl, p1);
        m2 = fmaxf(excl, p2);
        m3 = fmaxf(excl, p3);
    }

    float* orow = out + (size_t)bd * (NN * NN) + (size_t)(base + 15) * NN;

    #pragma unroll
    for (int k = 15; k >= 0; --k) {
        const int i = base + k;

        // Broadcast x[i]: component k&3 of lane srcq + (k>>2)  (compile-time select).
        const float xc = ((k & 3) == 0) ? xv.x : ((k & 3) == 1) ? xv.y
                                        : ((k & 3) == 2) ? xv.z : xv.w;
        const float xi = __shfl_sync(0xffffffffu, xc, srcq + (k >> 2));

        // m(i,j) = max(x[i], m(i+1,j)); exact reset at j == i.
        m0 = fmaxf(xi, m0);
        m1 = fmaxf(xi, m1);
        m2 = fmaxf(xi, m2);
        m3 = fmaxf(xi, m3);
        const bool hit = (lane == srcq + (k >> 2));
        if ((k & 3) == 0)      m0 = hit ? xi : m0;
        else if ((k & 3) == 1) m1 = hit ? xi : m1;
        else if ((k & 3) == 2) m2 = hit ? xi : m2;
        else                   m3 = hit ? xi : m3;

        // Sparse mask: nonzero ⇔ (unsigned)(j-i) < min(Ti, Tj).
        const unsigned o0 = (unsigned)(jb + 0 - i);
        const unsigned o1 = (unsigned)(jb + 1 - i);
        const unsigned o2 = (unsigned)(jb + 2 - i);
        const unsigned o3 = (unsigned)(jb + 3 - i);

        const int TiK = ti_of(k);  // compile-time constant per unrolled row
        float4 o4;
        if (TiK == 16) {           // odd rows: Tj >= 16 always => T = 16
            o4.x = (o0 < 16u) ? m0 : 0.0f;
            o4.y = (o1 < 16u) ? m1 : 0.0f;
            o4.z = (o2 < 16u) ? m2 : 0.0f;
            o4.w = (o3 < 16u) ? m3 : 0.0f;
        } else if (TiK == 128) {   // i ≡ 0 (mod 8): T = Tj
            o4.x = (o0 < Tj0) ? m0 : 0.0f;
            o4.y = (o1 < Tj1) ? m1 : 0.0f;
            o4.z = (o2 < Tj2) ? m2 : 0.0f;
            o4.w = (o3 < Tj3) ? m3 : 0.0f;
        } else {
            o4.x = (o0 < min((unsigned)TiK, Tj0)) ? m0 : 0.0f;
            o4.y = (o1 < min((unsigned)TiK, Tj1)) ? m1 : 0.0f;
            o4.z = (o2 < min((unsigned)TiK, Tj2)) ? m2 : 0.0f;
            o4.w = (o3 < min((unsigned)TiK, Tj3)) ? m3 : 0.0f;
        }

        __stcs((float4*)(orow + jb), o4);  // streaming store: output never re-read
        orow -= NN;
    }
}

extern "C" void kernel_launch(void* const* d_in, const int* in_sizes, int n_in,
                              void* d_out, int out_size) {
    const float* x = (const float*)d_in[0];
    float* out = (float*)d_out;
    const int n_bd = in_sizes[0] / NN;  // 16*256 = 4096 (b,d) rows
    sparse_maxpool_kernel<<<n_bd, 256>>>(x, out);
}

// round 10
// speedup vs baseline: 1.0109x; 1.0109x over previous
#include <cuda_runtime.h>
#include <cfloat>

#define NN 128

// Ti(k) = 16 << min(3, ctz(base+k)) with base ≡ 0 (mod 16)  => depends only on k=i&15.
__device__ __forceinline__ constexpr int ti_of(int k) {
    return (k == 0 || k == 8) ? 128 : (k & 1) ? 16 : (k & 2) ? 32 : 64;
}

__global__ void __launch_bounds__(256)
sparse_maxpool_kernel(const float* __restrict__ x, float* __restrict__ out) {
    const int bd   = blockIdx.x;            // one (b,d) pair per block
    const int warp = threadIdx.x >> 5;      // 8 warps, warp w owns rows [16w, 16w+15]
    const int lane = threadIdx.x & 31;
    const int jb   = lane << 2;             // this lane's 4 columns: jb..jb+3
    const int base = warp << 4;
    const int srcq = base >> 2;             // lane index holding x[base..base+3]

    // Every lane loads its 4 columns of x (512B row; L1-broadcast across warps).
    const float4 xv = __ldg(((const float4*)(x + (size_t)bd * NN)) + lane);

    // Per-element column thresholds: Tj = 16 << min(3, ctz(j+1)), loop-invariant.
    const unsigned Tj0 = 16u << min(3, __ffs(jb + 1) - 1);
    const unsigned Tj1 = 16u << min(3, __ffs(jb + 2) - 1);
    const unsigned Tj2 = 16u << min(3, __ffs(jb + 3) - 1);
    const unsigned Tj3 = 16u << min(3, __ffs(jb + 4) - 1);

    // Init m_e = max(x[base+16 .. j_e]) for j_e >= base+16, else -inf.
    float m0, m1, m2, m3;
    {
        const bool keep = (lane >= srcq + 4);
        float p0 = keep ? xv.x : -FLT_MAX;
        float p1 = fmaxf(p0, keep ? xv.y : -FLT_MAX);
        float p2 = fmaxf(p1, keep ? xv.z : -FLT_MAX);
        float p3 = fmaxf(p2, keep ? xv.w : -FLT_MAX);
        float s = p3;
        #pragma unroll
        for (int d = 1; d < 32; d <<= 1) {
            float u = __shfl_up_sync(0xffffffffu, s, d);
            if (lane >= d) s = fmaxf(s, u);
        }
        float excl = __shfl_up_sync(0xffffffffu, s, 1);
        if (lane == 0) excl = -FLT_MAX;
        m0 = fmaxf(excl, p0);
        m1 = fmaxf(excl, p1);
        m2 = fmaxf(excl, p2);
        m3 = fmaxf(excl, p3);
    }

    float* orow = out + (size_t)bd * (NN * NN) + (size_t)(base + 15) * NN;

    #pragma unroll
    for (int k = 15; k >= 0; --k) {
        const int i = base + k;

        // Broadcast x[i]: component k&3 of lane srcq + (k>>2)  (compile-time select).
        const float xc = ((k & 3) == 0) ? xv.x : ((k & 3) == 1) ? xv.y
                                        : ((k & 3) == 2) ? xv.z : xv.w;
        const float xi = __shfl_sync(0xffffffffu, xc, srcq + (k >> 2));

        // m(i,j) = max(x[i], m(i+1,j)); exact reset at j == i.
        m0 = fmaxf(xi, m0);
        m1 = fmaxf(xi, m1);
        m2 = fmaxf(xi, m2);
        m3 = fmaxf(xi, m3);
        const bool hit = (lane == srcq + (k >> 2));
        if ((k & 3) == 0)      m0 = hit ? xi : m0;
        else if ((k & 3) == 1) m1 = hit ? xi : m1;
        else if ((k & 3) == 2) m2 = hit ? xi : m2;
        else                   m3 = hit ? xi : m3;

        // Sparse mask: nonzero ⇔ (unsigned)(j-i) < min(Ti, Tj).
        const unsigned o0 = (unsigned)(jb + 0 - i);
        const unsigned o1 = (unsigned)(jb + 1 - i);
        const unsigned o2 = (unsigned)(jb + 2 - i);
        const unsigned o3 = (unsigned)(jb + 3 - i);

        const int TiK = ti_of(k);  // compile-time constant per unrolled row
        float4 o4;
        if (TiK == 16) {           // odd rows: Tj >= 16 always => T = 16
            o4.x = (o0 < 16u) ? m0 : 0.0f;
            o4.y = (o1 < 16u) ? m1 : 0.0f;
            o4.z = (o2 < 16u) ? m2 : 0.0f;
            o4.w = (o3 < 16u) ? m3 : 0.0f;
        } else if (TiK == 128) {   // i ≡ 0 (mod 8): T = Tj
            o4.x = (o0 < Tj0) ? m0 : 0.0f;
            o4.y = (o1 < Tj1) ? m1 : 0.0f;
            o4.z = (o2 < Tj2) ? m2 : 0.0f;
            o4.w = (o3 < Tj3) ? m3 : 0.0f;
        } else {
            o4.x = (o0 < min((unsigned)TiK, Tj0)) ? m0 : 0.0f;
            o4.y = (o1 < min((unsigned)TiK, Tj1)) ? m1 : 0.0f;
            o4.z = (o2 < min((unsigned)TiK, Tj2)) ? m2 : 0.0f;
            o4.w = (o3 < min((unsigned)TiK, Tj3)) ? m3 : 0.0f;
        }

        __stcs((float4*)(orow + jb), o4);  // streaming store: output never re-read
        orow -= NN;
    }
}

extern "C" void kernel_launch(void* const* d_in, const int* in_sizes, int n_in,
                              void* d_out, int out_size) {
    const float* x = (const float*)d_in[0];
    float* out = (float*)d_out;
    const int n_bd = in_sizes[0] / NN;  // 16*256 = 4096 (b,d) rows
    sparse_maxpool_kernel<<<n_bd, 256>>>(x, out);
}